// round 1
// baseline (speedup 1.0000x reference)
#include <cuda_runtime.h>

// result = sum_j W[j] * S_j / T_j
//   T_j = sum_n y_true[n][j]
//   S_j = sum_n |y_true[n][j] - y_preds[n][j]|
// (the 1/N factors of both means cancel exactly)

__device__ float g_T[5];
__device__ float g_S[5];

__constant__ float c_W[5] = {0.3f, 0.175f, 0.175f, 0.175f, 0.175f};

__global__ void zero_sums_kernel() {
    if (threadIdx.x < 5) {
        g_T[threadIdx.x] = 0.0f;
        g_S[threadIdx.x] = 0.0f;
    }
}

// Requires (gridDim.x * blockDim.x) % 5 == 0 so that each thread's 4
// element columns (flat_idx % 5) are the same on every grid-stride iteration.
__global__ void __launch_bounds__(256) reduce_kernel(
    const float4* __restrict__ yt,
    const float4* __restrict__ yp,
    int n4)
{
    const int tid    = blockIdx.x * blockDim.x + threadIdx.x;
    const int stride = gridDim.x * blockDim.x;

    float aT0 = 0.f, aT1 = 0.f, aT2 = 0.f, aT3 = 0.f;
    float aS0 = 0.f, aS1 = 0.f, aS2 = 0.f, aS3 = 0.f;

    for (int i = tid; i < n4; i += stride) {
        float4 t = __ldcs(yt + i);
        float4 p = __ldcs(yp + i);
        aT0 += t.x;  aS0 += fabsf(t.x - p.x);
        aT1 += t.y;  aS1 += fabsf(t.y - p.y);
        aT2 += t.z;  aS2 += fabsf(t.z - p.z);
        aT3 += t.w;  aS3 += fabsf(t.w - p.w);
    }

    __shared__ float sT[5];
    __shared__ float sS[5];
    if (threadIdx.x < 5) { sT[threadIdx.x] = 0.f; sS[threadIdx.x] = 0.f; }
    __syncthreads();

    // Column of element e of this thread's float4 slots (fixed across iters
    // because 4*stride % 5 == 0).
    const int base = tid * 4;  // flat element index of slot 0 (first iter)
    const int c0 = base % 5;
    const int c1 = (c0 + 1) % 5;
    const int c2 = (c0 + 2) % 5;
    const int c3 = (c0 + 3) % 5;

    atomicAdd(&sT[c0], aT0);  atomicAdd(&sS[c0], aS0);
    atomicAdd(&sT[c1], aT1);  atomicAdd(&sS[c1], aS1);
    atomicAdd(&sT[c2], aT2);  atomicAdd(&sS[c2], aS2);
    atomicAdd(&sT[c3], aT3);  atomicAdd(&sS[c3], aS3);
    __syncthreads();

    if (threadIdx.x < 5) {
        atomicAdd(&g_T[threadIdx.x], sT[threadIdx.x]);
        atomicAdd(&g_S[threadIdx.x], sS[threadIdx.x]);
    }
}

__global__ void finalize_kernel(float* __restrict__ out) {
    if (threadIdx.x == 0 && blockIdx.x == 0) {
        float r = 0.f;
        #pragma unroll
        for (int j = 0; j < 5; j++)
            r += c_W[j] * g_S[j] / g_T[j];
        out[0] = r;
    }
}

extern "C" void kernel_launch(void* const* d_in, const int* in_sizes, int n_in,
                              void* d_out, int out_size) {
    const float4* yt = (const float4*)d_in[0];
    const float4* yp = (const float4*)d_in[1];
    float* out = (float*)d_out;

    const int n  = in_sizes[0];   // 4194304 * 5 = 20971520 floats
    const int n4 = n / 4;         // 5242880 float4s (n % 4 == 0 here)

    const int BLOCK  = 256;
    const int BLOCKS = 1480;      // 1480*256 = 378880, divisible by 5

    zero_sums_kernel<<<1, 32>>>();
    reduce_kernel<<<BLOCKS, BLOCK>>>(yt, yp, n4);
    finalize_kernel<<<1, 32>>>(out);
}

// round 2
// speedup vs baseline: 1.1112x; 1.1112x over previous
#include <cuda_runtime.h>

// result = sum_j W[j] * S_j / T_j
//   T_j = sum_n y_true[n][j],  S_j = sum_n |y_true[n][j] - y_preds[n][j]|
// (the 1/N of both means cancels)
//
// Single fused kernel: grid-wide atomic accumulation into __device__ scratch,
// last block finishes (computes output, resets scratch to zero so the next
// graph replay sees a clean state -> deterministic).

__device__ float g_T[5] = {0.f, 0.f, 0.f, 0.f, 0.f};
__device__ float g_S[5] = {0.f, 0.f, 0.f, 0.f, 0.f};
__device__ unsigned int g_count = 0;

__constant__ float c_W[5] = {0.3f, 0.175f, 0.175f, 0.175f, 0.175f};

// Requires (gridDim.x * blockDim.x) % 5 == 0 so each thread's 4 float4-lane
// columns (flat_idx % 5) are invariant across grid-stride iterations.
__global__ void __launch_bounds__(256) fused_loss_kernel(
    const float4* __restrict__ yt,
    const float4* __restrict__ yp,
    int n4,
    float* __restrict__ out)
{
    const int tid    = blockIdx.x * blockDim.x + threadIdx.x;
    const int stride = gridDim.x * blockDim.x;

    float aT0 = 0.f, aT1 = 0.f, aT2 = 0.f, aT3 = 0.f;
    float aS0 = 0.f, aS1 = 0.f, aS2 = 0.f, aS3 = 0.f;

    int i = tid;
    // Unroll-by-4: 8 independent 16B loads in flight per thread.
    for (; i + 3 * stride < n4; i += 4 * stride) {
        float4 t0 = __ldcs(yt + i);
        float4 t1 = __ldcs(yt + i + stride);
        float4 t2 = __ldcs(yt + i + 2 * stride);
        float4 t3 = __ldcs(yt + i + 3 * stride);
        float4 p0 = __ldcs(yp + i);
        float4 p1 = __ldcs(yp + i + stride);
        float4 p2 = __ldcs(yp + i + 2 * stride);
        float4 p3 = __ldcs(yp + i + 3 * stride);

        aT0 += t0.x; aS0 += fabsf(t0.x - p0.x);
        aT1 += t0.y; aS1 += fabsf(t0.y - p0.y);
        aT2 += t0.z; aS2 += fabsf(t0.z - p0.z);
        aT3 += t0.w; aS3 += fabsf(t0.w - p0.w);

        aT0 += t1.x; aS0 += fabsf(t1.x - p1.x);
        aT1 += t1.y; aS1 += fabsf(t1.y - p1.y);
        aT2 += t1.z; aS2 += fabsf(t1.z - p1.z);
        aT3 += t1.w; aS3 += fabsf(t1.w - p1.w);

        aT0 += t2.x; aS0 += fabsf(t2.x - p2.x);
        aT1 += t2.y; aS1 += fabsf(t2.y - p2.y);
        aT2 += t2.z; aS2 += fabsf(t2.z - p2.z);
        aT3 += t2.w; aS3 += fabsf(t2.w - p2.w);

        aT0 += t3.x; aS0 += fabsf(t3.x - p3.x);
        aT1 += t3.y; aS1 += fabsf(t3.y - p3.y);
        aT2 += t3.z; aS2 += fabsf(t3.z - p3.z);
        aT3 += t3.w; aS3 += fabsf(t3.w - p3.w);
    }
    for (; i < n4; i += stride) {
        float4 t = __ldcs(yt + i);
        float4 p = __ldcs(yp + i);
        aT0 += t.x; aS0 += fabsf(t.x - p.x);
        aT1 += t.y; aS1 += fabsf(t.y - p.y);
        aT2 += t.z; aS2 += fabsf(t.z - p.z);
        aT3 += t.w; aS3 += fabsf(t.w - p.w);
    }

    // Block-level reduction into shared, keyed by column (flat index % 5).
    __shared__ float sT[5];
    __shared__ float sS[5];
    __shared__ bool  is_last;
    if (threadIdx.x < 5) { sT[threadIdx.x] = 0.f; sS[threadIdx.x] = 0.f; }
    __syncthreads();

    const int c0 = (tid * 4) % 5;
    const int c1 = (c0 + 1) % 5;
    const int c2 = (c0 + 2) % 5;
    const int c3 = (c0 + 3) % 5;

    atomicAdd(&sT[c0], aT0);  atomicAdd(&sS[c0], aS0);
    atomicAdd(&sT[c1], aT1);  atomicAdd(&sS[c1], aS1);
    atomicAdd(&sT[c2], aT2);  atomicAdd(&sS[c2], aS2);
    atomicAdd(&sT[c3], aT3);  atomicAdd(&sS[c3], aS3);
    __syncthreads();

    if (threadIdx.x < 5) {
        atomicAdd(&g_T[threadIdx.x], sT[threadIdx.x]);
        atomicAdd(&g_S[threadIdx.x], sS[threadIdx.x]);
    }
    __threadfence();

    if (threadIdx.x == 0) {
        unsigned int c = atomicAdd(&g_count, 1u);
        is_last = (c == gridDim.x - 1);
    }
    __syncthreads();

    if (is_last && threadIdx.x == 0) {
        // Read via atomicAdd(ptr, 0) so we see L2-resident atomic results
        // (plain LDG could be served from a stale L1 line).
        float r = 0.f;
        #pragma unroll
        for (int j = 0; j < 5; j++) {
            float T = atomicAdd(&g_T[j], 0.f);
            float S = atomicAdd(&g_S[j], 0.f);
            r += c_W[j] * S / T;
        }
        out[0] = r;
        // Reset for the next graph replay (deterministic across replays).
        #pragma unroll
        for (int j = 0; j < 5; j++) { g_T[j] = 0.f; g_S[j] = 0.f; }
        g_count = 0u;
        __threadfence();
    }
}

extern "C" void kernel_launch(void* const* d_in, const int* in_sizes, int n_in,
                              void* d_out, int out_size) {
    const float4* yt = (const float4*)d_in[0];
    const float4* yp = (const float4*)d_in[1];
    float* out = (float*)d_out;

    const int n  = in_sizes[0];   // 20971520 floats
    const int n4 = n / 4;         // 5242880 float4s

    // Single wave: 1180 blocks <= 148 SMs * 8 resident blocks (256 thr, low regs).
    // 1180*256 = 302080 threads, divisible by 5 (column-invariance requirement).
    const int BLOCK  = 256;
    const int BLOCKS = 1180;

    fused_loss_kernel<<<BLOCKS, BLOCK>>>(yt, yp, n4, out);
}

// round 3
// speedup vs baseline: 1.4689x; 1.3219x over previous
#include <cuda_runtime.h>

// result = sum_j W[j] * S_j / T_j
//   T_j = sum_n y_true[n][j],  S_j = sum_n |y_true[n][j] - y_preds[n][j]|
// (the 1/N of both means cancels)

__device__ float g_T[5] = {0.f, 0.f, 0.f, 0.f, 0.f};
__device__ float g_S[5] = {0.f, 0.f, 0.f, 0.f, 0.f};
__device__ unsigned int g_count = 0;

__constant__ float c_W[5] = {0.3f, 0.175f, 0.175f, 0.175f, 0.175f};

// __launch_bounds__(256, 4): cap 4 blocks/SM -> 64 regs/thread budget so the
// 8 LDG.128 of the unrolled body can be front-batched (MLP_p1 = 8). At 34
// regs (previous round) ptxas serialized the loads -> DRAM stuck at 37%.
// Requires (gridDim.x * blockDim.x) % 5 == 0 so each thread's 4 float4-lane
// columns (flat_idx % 5) are invariant across grid-stride iterations.
__global__ void __launch_bounds__(256, 4) fused_loss_kernel(
    const float4* __restrict__ yt,
    const float4* __restrict__ yp,
    int n4,
    float* __restrict__ out)
{
    const int tid    = blockIdx.x * blockDim.x + threadIdx.x;
    const int stride = gridDim.x * blockDim.x;

    float aT0 = 0.f, aT1 = 0.f, aT2 = 0.f, aT3 = 0.f;
    float aS0 = 0.f, aS1 = 0.f, aS2 = 0.f, aS3 = 0.f;

    int i = tid;
    for (; i + 3 * stride < n4; i += 4 * stride) {
        // ---- load phase: 8 independent LDG.128 in flight ----
        float4 t[4], p[4];
        #pragma unroll
        for (int k = 0; k < 4; k++) t[k] = __ldcs(yt + i + k * stride);
        #pragma unroll
        for (int k = 0; k < 4; k++) p[k] = __ldcs(yp + i + k * stride);

        // ---- compute phase ----
        #pragma unroll
        for (int k = 0; k < 4; k++) {
            aT0 += t[k].x; aS0 += fabsf(t[k].x - p[k].x);
            aT1 += t[k].y; aS1 += fabsf(t[k].y - p[k].y);
            aT2 += t[k].z; aS2 += fabsf(t[k].z - p[k].z);
            aT3 += t[k].w; aS3 += fabsf(t[k].w - p[k].w);
        }
    }
    for (; i < n4; i += stride) {
        float4 t = __ldcs(yt + i);
        float4 p = __ldcs(yp + i);
        aT0 += t.x; aS0 += fabsf(t.x - p.x);
        aT1 += t.y; aS1 += fabsf(t.y - p.y);
        aT2 += t.z; aS2 += fabsf(t.z - p.z);
        aT3 += t.w; aS3 += fabsf(t.w - p.w);
    }

    // Block-level reduction into shared, keyed by column (flat index % 5).
    __shared__ float sT[5];
    __shared__ float sS[5];
    __shared__ bool  is_last;
    if (threadIdx.x < 5) { sT[threadIdx.x] = 0.f; sS[threadIdx.x] = 0.f; }
    __syncthreads();

    const int c0 = (tid * 4) % 5;
    const int c1 = (c0 + 1) % 5;
    const int c2 = (c0 + 2) % 5;
    const int c3 = (c0 + 3) % 5;

    atomicAdd(&sT[c0], aT0);  atomicAdd(&sS[c0], aS0);
    atomicAdd(&sT[c1], aT1);  atomicAdd(&sS[c1], aS1);
    atomicAdd(&sT[c2], aT2);  atomicAdd(&sS[c2], aS2);
    atomicAdd(&sT[c3], aT3);  atomicAdd(&sS[c3], aS3);
    __syncthreads();

    if (threadIdx.x < 5) {
        atomicAdd(&g_T[threadIdx.x], sT[threadIdx.x]);
        atomicAdd(&g_S[threadIdx.x], sS[threadIdx.x]);
    }
    __threadfence();

    if (threadIdx.x == 0) {
        unsigned int c = atomicAdd(&g_count, 1u);
        is_last = (c == gridDim.x - 1);
    }
    __syncthreads();

    if (is_last && threadIdx.x == 0) {
        float r = 0.f;
        #pragma unroll
        for (int j = 0; j < 5; j++) {
            float T = atomicAdd(&g_T[j], 0.f);
            float S = atomicAdd(&g_S[j], 0.f);
            r += c_W[j] * S / T;
        }
        out[0] = r;
        // Reset for the next graph replay (deterministic across replays).
        #pragma unroll
        for (int j = 0; j < 5; j++) { g_T[j] = 0.f; g_S[j] = 0.f; }
        g_count = 0u;
        __threadfence();
    }
}

extern "C" void kernel_launch(void* const* d_in, const int* in_sizes, int n_in,
                              void* d_out, int out_size) {
    const float4* yt = (const float4*)d_in[0];
    const float4* yp = (const float4*)d_in[1];
    float* out = (float*)d_out;

    const int n  = in_sizes[0];   // 20971520 floats
    const int n4 = n / 4;         // 5242880 float4s

    // Single wave at 4 blocks/SM: 590 <= 4*148 = 592.
    // 590*256 = 151040 threads, divisible by 5 (column-invariance requirement).
    const int BLOCK  = 256;
    const int BLOCKS = 590;

    fused_loss_kernel<<<BLOCKS, BLOCK>>>(yt, yp, n4, out);
}

// round 4
// speedup vs baseline: 1.4918x; 1.0156x over previous
#include <cuda_runtime.h>

// result = sum_j W[j] * S_j / T_j
//   T_j = sum_n y_true[n][j],  S_j = sum_n |y_true[n][j] - y_preds[n][j]|
// (the 1/N of both means cancels)

__device__ float g_T[5] = {0.f, 0.f, 0.f, 0.f, 0.f};
__device__ float g_S[5] = {0.f, 0.f, 0.f, 0.f, 0.f};
__device__ unsigned int g_count = 0;

__constant__ float c_W[5] = {0.3f, 0.175f, 0.175f, 0.175f, 0.175f};

#define UNROLL 8

// __launch_bounds__(256, 3): 85-reg budget so the 16 LDG.128 of the unroll-8
// body stay front-batched in registers (16 float4 = 64 regs + accums + idx).
// In-flight LDG.128 per SM: 24 warps x 16 = 384 (R3 had 256 -> DRAM 52.7%).
// Requires (gridDim.x * blockDim.x) % 5 == 0 so each thread's 4 float4-lane
// columns (flat_idx % 5) are invariant across grid-stride iterations.
__global__ void __launch_bounds__(256, 3) fused_loss_kernel(
    const float4* __restrict__ yt,
    const float4* __restrict__ yp,
    int n4,
    float* __restrict__ out)
{
    const int tid    = blockIdx.x * blockDim.x + threadIdx.x;
    const int stride = gridDim.x * blockDim.x;

    float aT0 = 0.f, aT1 = 0.f, aT2 = 0.f, aT3 = 0.f;
    float aS0 = 0.f, aS1 = 0.f, aS2 = 0.f, aS3 = 0.f;

    int i = tid;
    for (; i + (UNROLL - 1) * stride < n4; i += UNROLL * stride) {
        // ---- load phase: 16 independent LDG.128 in flight ----
        float4 t[UNROLL], p[UNROLL];
        #pragma unroll
        for (int k = 0; k < UNROLL; k++) t[k] = __ldcs(yt + i + k * stride);
        #pragma unroll
        for (int k = 0; k < UNROLL; k++) p[k] = __ldcs(yp + i + k * stride);

        // ---- compute phase ----
        #pragma unroll
        for (int k = 0; k < UNROLL; k++) {
            aT0 += t[k].x; aS0 += fabsf(t[k].x - p[k].x);
            aT1 += t[k].y; aS1 += fabsf(t[k].y - p[k].y);
            aT2 += t[k].z; aS2 += fabsf(t[k].z - p[k].z);
            aT3 += t[k].w; aS3 += fabsf(t[k].w - p[k].w);
        }
    }
    for (; i < n4; i += stride) {
        float4 t = __ldcs(yt + i);
        float4 p = __ldcs(yp + i);
        aT0 += t.x; aS0 += fabsf(t.x - p.x);
        aT1 += t.y; aS1 += fabsf(t.y - p.y);
        aT2 += t.z; aS2 += fabsf(t.z - p.z);
        aT3 += t.w; aS3 += fabsf(t.w - p.w);
    }

    // Block-level reduction into shared, keyed by column (flat index % 5).
    __shared__ float sT[5];
    __shared__ float sS[5];
    __shared__ bool  is_last;
    if (threadIdx.x < 5) { sT[threadIdx.x] = 0.f; sS[threadIdx.x] = 0.f; }
    __syncthreads();

    const int c0 = (tid * 4) % 5;
    const int c1 = (c0 + 1) % 5;
    const int c2 = (c0 + 2) % 5;
    const int c3 = (c0 + 3) % 5;

    atomicAdd(&sT[c0], aT0);  atomicAdd(&sS[c0], aS0);
    atomicAdd(&sT[c1], aT1);  atomicAdd(&sS[c1], aS1);
    atomicAdd(&sT[c2], aT2);  atomicAdd(&sS[c2], aS2);
    atomicAdd(&sT[c3], aT3);  atomicAdd(&sS[c3], aS3);
    __syncthreads();

    if (threadIdx.x < 5) {
        atomicAdd(&g_T[threadIdx.x], sT[threadIdx.x]);
        atomicAdd(&g_S[threadIdx.x], sS[threadIdx.x]);
    }
    __threadfence();

    if (threadIdx.x == 0) {
        unsigned int c = atomicAdd(&g_count, 1u);
        is_last = (c == gridDim.x - 1);
    }
    __syncthreads();

    if (is_last && threadIdx.x == 0) {
        float r = 0.f;
        #pragma unroll
        for (int j = 0; j < 5; j++) {
            float T = atomicAdd(&g_T[j], 0.f);
            float S = atomicAdd(&g_S[j], 0.f);
            r += c_W[j] * S / T;
        }
        out[0] = r;
        // Reset for the next graph replay (deterministic across replays).
        #pragma unroll
        for (int j = 0; j < 5; j++) { g_T[j] = 0.f; g_S[j] = 0.f; }
        g_count = 0u;
        __threadfence();
    }
}

extern "C" void kernel_launch(void* const* d_in, const int* in_sizes, int n_in,
                              void* d_out, int out_size) {
    const float4* yt = (const float4*)d_in[0];
    const float4* yp = (const float4*)d_in[1];
    float* out = (float*)d_out;

    const int n  = in_sizes[0];   // 20971520 floats
    const int n4 = n / 4;         // 5242880 float4s

    // Single wave at 3 blocks/SM: 440 <= 3*148 = 444.
    // 440*256 = 112640 threads, divisible by 5 (column-invariance requirement).
    const int BLOCK  = 256;
    const int BLOCKS = 440;

    fused_loss_kernel<<<BLOCKS, BLOCK>>>(yt, yp, n4, out);
}

// round 5
// speedup vs baseline: 1.8271x; 1.2247x over previous
#include <cuda_runtime.h>
#include <cstdint>

// result = sum_j W[j] * S_j / T_j
//   T_j = sum_n y_true[n][j],  S_j = sum_n |y_true[n][j] - y_preds[n][j]|
//
// TMA (cp.async.bulk) streaming pipeline: the register LDG path saturated at
// 4.18 TB/s (R3==R4 despite 1.5x in-flight); bulk-copy GMEM->SMEM uses the
// async-proxy path which reaches the LTS cap (~6300 B/cyc chip).

__device__ float g_T[5] = {0.f, 0.f, 0.f, 0.f, 0.f};
__device__ float g_S[5] = {0.f, 0.f, 0.f, 0.f, 0.f};
__device__ unsigned int g_count = 0;

__constant__ float c_W[5] = {0.3f, 0.175f, 0.175f, 0.175f, 0.175f};

#define NSTAGES      4
#define CHUNK_FLOATS 5120                  // divisible by 5 -> chunk col-phase 0
#define CHUNK_BYTES  (CHUNK_FLOATS * 4)    // 20480
#define STAGE_BYTES  (2 * CHUNK_BYTES)     // 40960 (yt chunk + yp chunk)
#define SMEM_BYTES   (NSTAGES * STAGE_BYTES)  // 163840
#define NBLOCKS      148
#define NTHREADS     640                   // 640*8 = 5120 floats per chunk

static __device__ __forceinline__ uint32_t s2u(const void* p) {
    return (uint32_t)__cvta_generic_to_shared(p);
}

static __device__ __forceinline__ void mbar_init(uint32_t mbar, uint32_t count) {
    asm volatile("mbarrier.init.shared.b64 [%0], %1;" :: "r"(mbar), "r"(count) : "memory");
}

static __device__ __forceinline__ void mbar_wait(uint32_t mbar, uint32_t phase) {
    uint32_t done;
    asm volatile(
        "{\n\t.reg .pred p;\n\t"
        "mbarrier.try_wait.parity.acquire.cta.shared::cta.b64 p, [%1], %2;\n\t"
        "selp.b32 %0, 1, 0, p;\n\t}"
        : "=r"(done) : "r"(mbar), "r"(phase) : "memory");
    while (!done) {
        asm volatile(
            "{\n\t.reg .pred p;\n\t"
            "mbarrier.try_wait.parity.acquire.cta.shared::cta.b64 p, [%1], %2, 0x989680;\n\t"
            "selp.b32 %0, 1, 0, p;\n\t}"
            : "=r"(done) : "r"(mbar), "r"(phase) : "memory");
    }
}

static __device__ __forceinline__ void issue_chunk(
    const char* __restrict__ yt, const char* __restrict__ yp,
    uint32_t stage_smem, uint32_t mbar, long long byte_off)
{
    asm volatile("mbarrier.arrive.expect_tx.shared.b64 _, [%0], %1;"
                 :: "r"(mbar), "r"((uint32_t)STAGE_BYTES) : "memory");
    asm volatile(
        "cp.async.bulk.shared::cluster.global.mbarrier::complete_tx::bytes [%0], [%1], %2, [%3];"
        :: "r"(stage_smem), "l"(yt + byte_off), "r"((uint32_t)CHUNK_BYTES), "r"(mbar) : "memory");
    asm volatile(
        "cp.async.bulk.shared::cluster.global.mbarrier::complete_tx::bytes [%0], [%1], %2, [%3];"
        :: "r"(stage_smem + CHUNK_BYTES), "l"(yp + byte_off), "r"((uint32_t)CHUNK_BYTES), "r"(mbar) : "memory");
}

// Rotate B[0..4] (column of B[j] is (c0+j)%5) into absolute columns.
#define ROT_CASE(C)                                                          \
    case C:                                                                  \
        cT[(C+0)%5]=BT[0]; cT[(C+1)%5]=BT[1]; cT[(C+2)%5]=BT[2];             \
        cT[(C+3)%5]=BT[3]; cT[(C+4)%5]=BT[4];                                \
        cS[(C+0)%5]=BS[0]; cS[(C+1)%5]=BS[1]; cS[(C+2)%5]=BS[2];             \
        cS[(C+3)%5]=BS[3]; cS[(C+4)%5]=BS[4];                                \
        break;

__global__ void __launch_bounds__(NTHREADS, 1) fused_loss_tma_kernel(
    const char* __restrict__ yt,
    const char* __restrict__ yp,
    int n_floats,
    float* __restrict__ out)
{
    extern __shared__ char dynbuf[];
    __shared__ unsigned long long full_bar[NSTAGES];
    __shared__ float sT[5];
    __shared__ float sS[5];
    __shared__ bool is_last;

    const int tid = threadIdx.x;
    const int bid = blockIdx.x;

    const int nchunks = n_floats / CHUNK_FLOATS;            // 4096 for real input
    // chunks for this block: c = bid, bid+NBLOCKS, ...
    const int cnt = (nchunks > bid) ? (nchunks - bid + NBLOCKS - 1) / NBLOCKS : 0;

    if (tid == 0) {
        #pragma unroll
        for (int s = 0; s < NSTAGES; s++) mbar_init(s2u(&full_bar[s]), 1);
    }
    if (tid < 5) { sT[tid] = 0.f; sS[tid] = 0.f; }
    __syncthreads();

    // Prologue: fill the pipeline.
    if (tid == 0) {
        const int pro = (cnt < NSTAGES) ? cnt : NSTAGES;
        for (int l = 0; l < pro; l++) {
            const long long c = (long long)bid + (long long)l * NBLOCKS;
            issue_chunk(yt, yp, s2u(dynbuf) + l * STAGE_BYTES, s2u(&full_bar[l]),
                        c * (long long)CHUNK_BYTES);
        }
    }

    // Fixed slot accumulators: slot k holds column (c0 + k) % 5, c0 = (8*tid)%5,
    // identical for every chunk because CHUNK_FLOATS % 5 == 0.
    float AT[8] = {0.f,0.f,0.f,0.f,0.f,0.f,0.f,0.f};
    float AS[8] = {0.f,0.f,0.f,0.f,0.f,0.f,0.f,0.f};

    for (int l = 0; l < cnt; l++) {
        const int s  = l & (NSTAGES - 1);
        const int ph = (l >> 2) & 1;
        mbar_wait(s2u(&full_bar[s]), ph);

        const float4* ts = (const float4*)(dynbuf + s * STAGE_BYTES);
        const float4* ps = (const float4*)(dynbuf + s * STAGE_BYTES + CHUNK_BYTES);
        const float4 t0 = ts[2 * tid], t1 = ts[2 * tid + 1];
        const float4 p0 = ps[2 * tid], p1 = ps[2 * tid + 1];

        AT[0] += t0.x; AS[0] += fabsf(t0.x - p0.x);
        AT[1] += t0.y; AS[1] += fabsf(t0.y - p0.y);
        AT[2] += t0.z; AS[2] += fabsf(t0.z - p0.z);
        AT[3] += t0.w; AS[3] += fabsf(t0.w - p0.w);
        AT[4] += t1.x; AS[4] += fabsf(t1.x - p1.x);
        AT[5] += t1.y; AS[5] += fabsf(t1.y - p1.y);
        AT[6] += t1.z; AS[6] += fabsf(t1.z - p1.z);
        AT[7] += t1.w; AS[7] += fabsf(t1.w - p1.w);

        __syncthreads();   // whole block done with stage s -> safe to refill

        if (tid == 0 && l + NSTAGES < cnt) {
            const long long c = (long long)bid + (long long)(l + NSTAGES) * NBLOCKS;
            issue_chunk(yt, yp, s2u(dynbuf) + s * STAGE_BYTES, s2u(&full_bar[s]),
                        c * (long long)CHUNK_BYTES);
        }
    }

    // Fold slots 5..7 into 0..2 (same column: offset 5 == 0 mod 5).
    float BT[5], BS[5];
    BT[0] = AT[0] + AT[5]; BS[0] = AS[0] + AS[5];
    BT[1] = AT[1] + AT[6]; BS[1] = AS[1] + AS[6];
    BT[2] = AT[2] + AT[7]; BS[2] = AS[2] + AS[7];
    BT[3] = AT[3];         BS[3] = AS[3];
    BT[4] = AT[4];         BS[4] = AS[4];

    // Rotate to absolute columns.
    float cT[5], cS[5];
    const int c0 = (tid * 8) % 5;
    switch (c0) {
        ROT_CASE(0) ROT_CASE(1) ROT_CASE(2) ROT_CASE(3) ROT_CASE(4)
        default: break;
    }

    // Warp butterfly reduction.
    #pragma unroll
    for (int off = 16; off > 0; off >>= 1) {
        #pragma unroll
        for (int j = 0; j < 5; j++) {
            cT[j] += __shfl_xor_sync(0xffffffffu, cT[j], off);
            cS[j] += __shfl_xor_sync(0xffffffffu, cS[j], off);
        }
    }
    if ((tid & 31) == 0) {
        #pragma unroll
        for (int j = 0; j < 5; j++) {
            atomicAdd(&sT[j], cT[j]);
            atomicAdd(&sS[j], cS[j]);
        }
    }
    __syncthreads();

    // Leftover floats (none for the real input; correctness guard).
    const int rem_start = nchunks * CHUNK_FLOATS;
    if (bid == 0 && tid == 0 && rem_start < n_floats) {
        const float* ytf = (const float*)yt;
        const float* ypf = (const float*)yp;
        for (int idx = rem_start; idx < n_floats; idx++) {
            const int c = idx % 5;
            atomicAdd(&g_T[c], ytf[idx]);
            atomicAdd(&g_S[c], fabsf(ytf[idx] - ypf[idx]));
        }
    }

    if (tid < 5) {
        atomicAdd(&g_T[tid], sT[tid]);
        atomicAdd(&g_S[tid], sS[tid]);
    }
    __threadfence();

    if (tid == 0) {
        const unsigned int c = atomicAdd(&g_count, 1u);
        is_last = (c == gridDim.x - 1);
    }
    __syncthreads();

    if (is_last && tid == 0) {
        float r = 0.f;
        #pragma unroll
        for (int j = 0; j < 5; j++) {
            const float T = atomicAdd(&g_T[j], 0.f);
            const float S = atomicAdd(&g_S[j], 0.f);
            r += c_W[j] * S / T;
        }
        out[0] = r;
        #pragma unroll
        for (int j = 0; j < 5; j++) { g_T[j] = 0.f; g_S[j] = 0.f; }
        g_count = 0u;
        __threadfence();
    }
}

extern "C" void kernel_launch(void* const* d_in, const int* in_sizes, int n_in,
                              void* d_out, int out_size) {
    const char* yt = (const char*)d_in[0];
    const char* yp = (const char*)d_in[1];
    float* out = (float*)d_out;
    const int n = in_sizes[0];   // 20971520 floats

    static bool attr_set = false;
    if (!attr_set) {
        cudaFuncSetAttribute(fused_loss_tma_kernel,
                             cudaFuncAttributeMaxDynamicSharedMemorySize, SMEM_BYTES);
        attr_set = true;
    }

    fused_loss_tma_kernel<<<NBLOCKS, NTHREADS, SMEM_BYTES>>>(yt, yp, n, out);
}

// round 6
// speedup vs baseline: 1.9289x; 1.0557x over previous
#include <cuda_runtime.h>
#include <cstdint>

// result = sum_j W[j] * S_j / T_j
//   T_j = sum_n y_true[n][j],  S_j = sum_n |y_true[n][j] - y_preds[n][j]|
//
// TMA (cp.async.bulk) streaming pipeline, 2 blocks per SM so the per-chunk
// barrier/wait bubbles of one pipeline are hidden by the other.

__device__ float g_T[5] = {0.f, 0.f, 0.f, 0.f, 0.f};
__device__ float g_S[5] = {0.f, 0.f, 0.f, 0.f, 0.f};
__device__ unsigned int g_count = 0;

__constant__ float c_W[5] = {0.3f, 0.175f, 0.175f, 0.175f, 0.175f};

#define NSTAGES      4
#define CHUNK_FLOATS 2560                  // 640 threads * 4 floats; % 5 == 0
#define CHUNK_BYTES  (CHUNK_FLOATS * 4)    // 10240
#define STAGE_BYTES  (2 * CHUNK_BYTES)     // 20480 (yt chunk + yp chunk)
#define SMEM_BYTES   (NSTAGES * STAGE_BYTES)  // 81920 -> 2 blocks/SM fit
#define NBLOCKS      296                   // 2 per SM, single wave
#define NTHREADS     640

static __device__ __forceinline__ uint32_t s2u(const void* p) {
    return (uint32_t)__cvta_generic_to_shared(p);
}

static __device__ __forceinline__ void mbar_init(uint32_t mbar, uint32_t count) {
    asm volatile("mbarrier.init.shared.b64 [%0], %1;" :: "r"(mbar), "r"(count) : "memory");
}

static __device__ __forceinline__ void mbar_wait(uint32_t mbar, uint32_t phase) {
    uint32_t done;
    asm volatile(
        "{\n\t.reg .pred p;\n\t"
        "mbarrier.try_wait.parity.acquire.cta.shared::cta.b64 p, [%1], %2;\n\t"
        "selp.b32 %0, 1, 0, p;\n\t}"
        : "=r"(done) : "r"(mbar), "r"(phase) : "memory");
    while (!done) {
        asm volatile(
            "{\n\t.reg .pred p;\n\t"
            "mbarrier.try_wait.parity.acquire.cta.shared::cta.b64 p, [%1], %2, 0x989680;\n\t"
            "selp.b32 %0, 1, 0, p;\n\t}"
            : "=r"(done) : "r"(mbar), "r"(phase) : "memory");
    }
}

static __device__ __forceinline__ void issue_chunk(
    const char* __restrict__ yt, const char* __restrict__ yp,
    uint32_t stage_smem, uint32_t mbar, long long byte_off)
{
    asm volatile("mbarrier.arrive.expect_tx.shared.b64 _, [%0], %1;"
                 :: "r"(mbar), "r"((uint32_t)STAGE_BYTES) : "memory");
    asm volatile(
        "cp.async.bulk.shared::cluster.global.mbarrier::complete_tx::bytes [%0], [%1], %2, [%3];"
        :: "r"(stage_smem), "l"(yt + byte_off), "r"((uint32_t)CHUNK_BYTES), "r"(mbar) : "memory");
    asm volatile(
        "cp.async.bulk.shared::cluster.global.mbarrier::complete_tx::bytes [%0], [%1], %2, [%3];"
        :: "r"(stage_smem + CHUNK_BYTES), "l"(yp + byte_off), "r"((uint32_t)CHUNK_BYTES), "r"(mbar) : "memory");
}

// Rotate 4 slot-accumulators (slot k holds column (c0+k)%5) into absolute cols.
#define ROT_CASE(C)                                                           \
    case C:                                                                   \
        cT[(C+0)%5]=AT[0]; cT[(C+1)%5]=AT[1]; cT[(C+2)%5]=AT[2];              \
        cT[(C+3)%5]=AT[3]; cT[(C+4)%5]=0.f;                                   \
        cS[(C+0)%5]=AS[0]; cS[(C+1)%5]=AS[1]; cS[(C+2)%5]=AS[2];              \
        cS[(C+3)%5]=AS[3]; cS[(C+4)%5]=0.f;                                   \
        break;

__global__ void __launch_bounds__(NTHREADS, 2) fused_loss_tma_kernel(
    const char* __restrict__ yt,
    const char* __restrict__ yp,
    int n_floats,
    float* __restrict__ out)
{
    extern __shared__ char dynbuf[];
    __shared__ unsigned long long full_bar[NSTAGES];
    __shared__ float sT[5];
    __shared__ float sS[5];
    __shared__ bool is_last;

    const int tid = threadIdx.x;
    const int bid = blockIdx.x;

    const int nchunks = n_floats / CHUNK_FLOATS;            // 8192 for real input
    const int cnt = (nchunks > bid) ? (nchunks - bid + NBLOCKS - 1) / NBLOCKS : 0;

    if (tid == 0) {
        #pragma unroll
        for (int s = 0; s < NSTAGES; s++) mbar_init(s2u(&full_bar[s]), 1);
    }
    if (tid < 5) { sT[tid] = 0.f; sS[tid] = 0.f; }
    __syncthreads();

    // Prologue: fill the pipeline.
    if (tid == 0) {
        const int pro = (cnt < NSTAGES) ? cnt : NSTAGES;
        for (int l = 0; l < pro; l++) {
            const long long c = (long long)bid + (long long)l * NBLOCKS;
            issue_chunk(yt, yp, s2u(dynbuf) + l * STAGE_BYTES, s2u(&full_bar[l]),
                        c * (long long)CHUNK_BYTES);
        }
    }

    // Slot k holds column (c0 + k) % 5, c0 = (4*tid) % 5, fixed across chunks
    // because CHUNK_FLOATS % 5 == 0.
    float AT[4] = {0.f, 0.f, 0.f, 0.f};
    float AS[4] = {0.f, 0.f, 0.f, 0.f};

    for (int l = 0; l < cnt; l++) {
        const int s  = l & (NSTAGES - 1);
        const int ph = (l >> 2) & 1;
        mbar_wait(s2u(&full_bar[s]), ph);

        const float4 t = ((const float4*)(dynbuf + s * STAGE_BYTES))[tid];
        const float4 p = ((const float4*)(dynbuf + s * STAGE_BYTES + CHUNK_BYTES))[tid];

        AT[0] += t.x; AS[0] += fabsf(t.x - p.x);
        AT[1] += t.y; AS[1] += fabsf(t.y - p.y);
        AT[2] += t.z; AS[2] += fabsf(t.z - p.z);
        AT[3] += t.w; AS[3] += fabsf(t.w - p.w);

        __syncthreads();   // whole block done with stage s -> safe to refill

        if (tid == 0 && l + NSTAGES < cnt) {
            const long long c = (long long)bid + (long long)(l + NSTAGES) * NBLOCKS;
            issue_chunk(yt, yp, s2u(dynbuf) + s * STAGE_BYTES, s2u(&full_bar[s]),
                        c * (long long)CHUNK_BYTES);
        }
    }

    // Rotate to absolute columns.
    float cT[5], cS[5];
    const int c0 = (tid * 4) % 5;
    switch (c0) {
        ROT_CASE(0) ROT_CASE(1) ROT_CASE(2) ROT_CASE(3) ROT_CASE(4)
        default: break;
    }

    // Warp butterfly reduction.
    #pragma unroll
    for (int off = 16; off > 0; off >>= 1) {
        #pragma unroll
        for (int j = 0; j < 5; j++) {
            cT[j] += __shfl_xor_sync(0xffffffffu, cT[j], off);
            cS[j] += __shfl_xor_sync(0xffffffffu, cS[j], off);
        }
    }
    if ((tid & 31) == 0) {
        #pragma unroll
        for (int j = 0; j < 5; j++) {
            atomicAdd(&sT[j], cT[j]);
            atomicAdd(&sS[j], cS[j]);
        }
    }
    __syncthreads();

    // Leftover floats (none for the real input; correctness guard).
    const int rem_start = nchunks * CHUNK_FLOATS;
    if (bid == 0 && tid == 0 && rem_start < n_floats) {
        const float* ytf = (const float*)yt;
        const float* ypf = (const float*)yp;
        for (int idx = rem_start; idx < n_floats; idx++) {
            const int c = idx % 5;
            atomicAdd(&g_T[c], ytf[idx]);
            atomicAdd(&g_S[c], fabsf(ytf[idx] - ypf[idx]));
        }
    }

    if (tid < 5) {
        atomicAdd(&g_T[tid], sT[tid]);
        atomicAdd(&g_S[tid], sS[tid]);
    }
    __threadfence();

    if (tid == 0) {
        const unsigned int c = atomicAdd(&g_count, 1u);
        is_last = (c == gridDim.x - 1);
    }
    __syncthreads();

    if (is_last && tid == 0) {
        float r = 0.f;
        #pragma unroll
        for (int j = 0; j < 5; j++) {
            const float T = atomicAdd(&g_T[j], 0.f);
            const float S = atomicAdd(&g_S[j], 0.f);
            r += c_W[j] * S / T;
        }
        out[0] = r;
        #pragma unroll
        for (int j = 0; j < 5; j++) { g_T[j] = 0.f; g_S[j] = 0.f; }
        g_count = 0u;
        __threadfence();
    }
}

extern "C" void kernel_launch(void* const* d_in, const int* in_sizes, int n_in,
                              void* d_out, int out_size) {
    const char* yt = (const char*)d_in[0];
    const char* yp = (const char*)d_in[1];
    float* out = (float*)d_out;
    const int n = in_sizes[0];   // 20971520 floats

    static bool attr_set = false;
    if (!attr_set) {
        cudaFuncSetAttribute(fused_loss_tma_kernel,
                             cudaFuncAttributeMaxDynamicSharedMemorySize, SMEM_BYTES);
        attr_set = true;
    }

    fused_loss_tma_kernel<<<NBLOCKS, NTHREADS, SMEM_BYTES>>>(yt, yp, n, out);
}

// round 7
// speedup vs baseline: 2.3679x; 1.2276x over previous
#include <cuda_runtime.h>
#include <cstdint>

// result = sum_j W[j] * S_j / T_j
//   T_j = sum_n y_true[n][j],  S_j = sum_n |y_true[n][j] - y_preds[n][j]|
//
// Hybrid streaming: first half of the data via a 4-stage TMA(cp.async.bulk)
// pipeline (solo cap measured 5.27 TB/s), second half via direct LDG.128
// (solo cap 4.18 TB/s) issued from the same threads so both request engines
// run concurrently against DRAM.

__device__ float g_T[5] = {0.f, 0.f, 0.f, 0.f, 0.f};
__device__ float g_S[5] = {0.f, 0.f, 0.f, 0.f, 0.f};
__device__ unsigned int g_count = 0;

__constant__ float c_W[5] = {0.3f, 0.175f, 0.175f, 0.175f, 0.175f};

#define NSTAGES      4
#define CHUNK_FLOATS 2560                  // 640 threads * 4 floats; % 5 == 0
#define CHUNK_BYTES  (CHUNK_FLOATS * 4)    // 10240
#define STAGE_BYTES  (2 * CHUNK_BYTES)     // 20480 (yt chunk + yp chunk)
#define SMEM_BYTES   (NSTAGES * STAGE_BYTES)  // 81920 -> 2 blocks/SM
#define NBLOCKS      296
#define NTHREADS     640
#define TOT_THREADS  (NBLOCKS * NTHREADS)  // 189440, % 5 == 0

static __device__ __forceinline__ uint32_t s2u(const void* p) {
    return (uint32_t)__cvta_generic_to_shared(p);
}

static __device__ __forceinline__ void mbar_init(uint32_t mbar, uint32_t count) {
    asm volatile("mbarrier.init.shared.b64 [%0], %1;" :: "r"(mbar), "r"(count) : "memory");
}

static __device__ __forceinline__ void mbar_wait(uint32_t mbar, uint32_t phase) {
    uint32_t done;
    asm volatile(
        "{\n\t.reg .pred p;\n\t"
        "mbarrier.try_wait.parity.acquire.cta.shared::cta.b64 p, [%1], %2;\n\t"
        "selp.b32 %0, 1, 0, p;\n\t}"
        : "=r"(done) : "r"(mbar), "r"(phase) : "memory");
    while (!done) {
        asm volatile(
            "{\n\t.reg .pred p;\n\t"
            "mbarrier.try_wait.parity.acquire.cta.shared::cta.b64 p, [%1], %2, 0x989680;\n\t"
            "selp.b32 %0, 1, 0, p;\n\t}"
            : "=r"(done) : "r"(mbar), "r"(phase) : "memory");
    }
}

static __device__ __forceinline__ void issue_chunk(
    const char* __restrict__ yt, const char* __restrict__ yp,
    uint32_t stage_smem, uint32_t mbar, long long byte_off)
{
    asm volatile("mbarrier.arrive.expect_tx.shared.b64 _, [%0], %1;"
                 :: "r"(mbar), "r"((uint32_t)STAGE_BYTES) : "memory");
    asm volatile(
        "cp.async.bulk.shared::cluster.global.mbarrier::complete_tx::bytes [%0], [%1], %2, [%3];"
        :: "r"(stage_smem), "l"(yt + byte_off), "r"((uint32_t)CHUNK_BYTES), "r"(mbar) : "memory");
    asm volatile(
        "cp.async.bulk.shared::cluster.global.mbarrier::complete_tx::bytes [%0], [%1], %2, [%3];"
        :: "r"(stage_smem + CHUNK_BYTES), "l"(yp + byte_off), "r"((uint32_t)CHUNK_BYTES), "r"(mbar) : "memory");
}

// Rotate 4 slot-accumulators (slot k holds column (c0+k)%5) into absolute cols.
#define ROT_CASE(C)                                                           \
    case C:                                                                   \
        cT[(C+0)%5]=AT[0]; cT[(C+1)%5]=AT[1]; cT[(C+2)%5]=AT[2];              \
        cT[(C+3)%5]=AT[3]; cT[(C+4)%5]=0.f;                                   \
        cS[(C+0)%5]=AS[0]; cS[(C+1)%5]=AS[1]; cS[(C+2)%5]=AS[2];              \
        cS[(C+3)%5]=AS[3]; cS[(C+4)%5]=0.f;                                   \
        break;

__global__ void __launch_bounds__(NTHREADS, 2) fused_loss_hybrid_kernel(
    const char* __restrict__ yt,
    const char* __restrict__ yp,
    int n_floats,
    float* __restrict__ out)
{
    extern __shared__ char dynbuf[];
    __shared__ unsigned long long full_bar[NSTAGES];
    __shared__ float sT[5];
    __shared__ float sS[5];
    __shared__ bool is_last;

    const int tid  = threadIdx.x;
    const int bid  = blockIdx.x;
    const int gtid = bid * NTHREADS + tid;

    // --- split: TMA covers [0, n_tma), LDG covers [n_tma, n) ---
    // CHUNK_FLOATS % 20 == 0 -> n_tma is 0 mod 4 and mod 5.
    const int nchunks = (n_floats / 2) / CHUNK_FLOATS;      // 4096 for real input
    const int n_tma   = nchunks * CHUNK_FLOATS;

    const int cnt = (nchunks > bid) ? (nchunks - bid + NBLOCKS - 1) / NBLOCKS : 0;

    const int ldg_start4 = n_tma / 4;
    const int ldg_end4   = n_floats / 4;
    const int span4      = ldg_end4 - ldg_start4 - gtid;    // my float4 slots
    const int lcnt = (span4 > 0) ? (span4 + TOT_THREADS - 1) / TOT_THREADS : 0;

    const int L = (cnt > lcnt) ? cnt : lcnt;

    if (tid == 0) {
        #pragma unroll
        for (int s = 0; s < NSTAGES; s++) mbar_init(s2u(&full_bar[s]), 1);
    }
    if (tid < 5) { sT[tid] = 0.f; sS[tid] = 0.f; }
    __syncthreads();

    // Prologue: fill the TMA pipeline.
    if (tid == 0) {
        const int pro = (cnt < NSTAGES) ? cnt : NSTAGES;
        for (int l = 0; l < pro; l++) {
            const long long c = (long long)bid + (long long)l * NBLOCKS;
            issue_chunk(yt, yp, s2u(dynbuf) + l * STAGE_BYTES, s2u(&full_bar[l]),
                        c * (long long)CHUNK_BYTES);
        }
    }

    // Shared slot accumulators: both the TMA chunk phase (4*tid mod 5; chunk
    // start == 0 mod 5) and the LDG phase (4*gtid mod 5; NTHREADS,n_tma,stride
    // all == 0 mod 5) equal c0 = (4*tid) % 5 -> slots are column-consistent.
    float AT[4] = {0.f, 0.f, 0.f, 0.f};
    float AS[4] = {0.f, 0.f, 0.f, 0.f};

    const float4* yt4 = (const float4*)yt;
    const float4* yp4 = (const float4*)yp;
    int i4 = ldg_start4 + gtid;

    for (int l = 0; l < L; l++) {
        // ---- issue LDG pair first so it overlaps the mbarrier wait ----
        float4 lt, lp;
        const bool dl = (l < lcnt);
        if (dl) {
            lt = __ldcs(yt4 + i4);
            lp = __ldcs(yp4 + i4);
            i4 += TOT_THREADS;
        }

        if (l < cnt) {
            const int s  = l & (NSTAGES - 1);
            const int ph = (l >> 2) & 1;
            mbar_wait(s2u(&full_bar[s]), ph);

            const float4 t = ((const float4*)(dynbuf + s * STAGE_BYTES))[tid];
            const float4 p = ((const float4*)(dynbuf + s * STAGE_BYTES + CHUNK_BYTES))[tid];
            AT[0] += t.x; AS[0] += fabsf(t.x - p.x);
            AT[1] += t.y; AS[1] += fabsf(t.y - p.y);
            AT[2] += t.z; AS[2] += fabsf(t.z - p.z);
            AT[3] += t.w; AS[3] += fabsf(t.w - p.w);
        }

        if (dl) {
            AT[0] += lt.x; AS[0] += fabsf(lt.x - lp.x);
            AT[1] += lt.y; AS[1] += fabsf(lt.y - lp.y);
            AT[2] += lt.z; AS[2] += fabsf(lt.z - lp.z);
            AT[3] += lt.w; AS[3] += fabsf(lt.w - lp.w);
        }

        if (l < cnt) {                 // cnt is block-uniform -> sync is uniform
            __syncthreads();           // whole block done with stage s
            if (tid == 0 && l + NSTAGES < cnt) {
                const int s = l & (NSTAGES - 1);
                const long long c = (long long)bid + (long long)(l + NSTAGES) * NBLOCKS;
                issue_chunk(yt, yp, s2u(dynbuf) + s * STAGE_BYTES, s2u(&full_bar[s]),
                            c * (long long)CHUNK_BYTES);
            }
        }
    }

    // Rotate to absolute columns.
    float cT[5], cS[5];
    const int c0 = (tid * 4) % 5;
    switch (c0) {
        ROT_CASE(0) ROT_CASE(1) ROT_CASE(2) ROT_CASE(3) ROT_CASE(4)
        default: break;
    }

    // Warp butterfly reduction.
    #pragma unroll
    for (int off = 16; off > 0; off >>= 1) {
        #pragma unroll
        for (int j = 0; j < 5; j++) {
            cT[j] += __shfl_xor_sync(0xffffffffu, cT[j], off);
            cS[j] += __shfl_xor_sync(0xffffffffu, cS[j], off);
        }
    }
    if ((tid & 31) == 0) {
        #pragma unroll
        for (int j = 0; j < 5; j++) {
            atomicAdd(&sT[j], cT[j]);
            atomicAdd(&sS[j], cS[j]);
        }
    }
    __syncthreads();

    // Scalar leftover (none for the real input; correctness guard).
    const int rem_start = (n_floats / 4) * 4;
    if (bid == 0 && tid == 0 && rem_start < n_floats) {
        const float* ytf = (const float*)yt;
        const float* ypf = (const float*)yp;
        for (int idx = rem_start; idx < n_floats; idx++) {
            const int c = idx % 5;
            atomicAdd(&g_T[c], ytf[idx]);
            atomicAdd(&g_S[c], fabsf(ytf[idx] - ypf[idx]));
        }
    }

    if (tid < 5) {
        atomicAdd(&g_T[tid], sT[tid]);
        atomicAdd(&g_S[tid], sS[tid]);
    }
    __threadfence();

    if (tid == 0) {
        const unsigned int c = atomicAdd(&g_count, 1u);
        is_last = (c == gridDim.x - 1);
    }
    __syncthreads();

    if (is_last && tid == 0) {
        float r = 0.f;
        #pragma unroll
        for (int j = 0; j < 5; j++) {
            const float T = atomicAdd(&g_T[j], 0.f);
            const float S = atomicAdd(&g_S[j], 0.f);
            r += c_W[j] * S / T;
        }
        out[0] = r;
        #pragma unroll
        for (int j = 0; j < 5; j++) { g_T[j] = 0.f; g_S[j] = 0.f; }
        g_count = 0u;
        __threadfence();
    }
}

extern "C" void kernel_launch(void* const* d_in, const int* in_sizes, int n_in,
                              void* d_out, int out_size) {
    const char* yt = (const char*)d_in[0];
    const char* yp = (const char*)d_in[1];
    float* out = (float*)d_out;
    const int n = in_sizes[0];   // 20971520 floats

    static bool attr_set = false;
    if (!attr_set) {
        cudaFuncSetAttribute(fused_loss_hybrid_kernel,
                             cudaFuncAttributeMaxDynamicSharedMemorySize, SMEM_BYTES);
        attr_set = true;
    }

    fused_loss_hybrid_kernel<<<NBLOCKS, NTHREADS, SMEM_BYTES>>>(yt, yp, n, out);
}